// round 3
// baseline (speedup 1.0000x reference)
#include <cuda_runtime.h>

#define N_NODES   100000
#define E_EDGES   1600000
#define H_DIM     128
#define L_LAYERS  4
#define C_CLASSES 12
#define G_GRAPHS  512
#define BN_EPS    1e-5f

// ---------------- device scratch (no allocation allowed) ----------------
__device__ __align__(128) float g_h  [N_NODES * H_DIM];   // activations
__device__ __align__(128) float g_hw [N_NODES * H_DIM];   // (h @ W) * dinv[row]
__device__ __align__(128) float g_agg[N_NODES * H_DIM];   // aggregation buffer
__device__ __align__(128) float g_dinv[N_NODES];
__device__ __align__(128) int   g_deg [N_NODES];
__device__ __align__(128) float g_pool[G_GRAPHS * H_DIM];
__device__ __align__(128) int   g_cnt [G_GRAPHS];

// ---------------- zero / degree / dinv ----------------
__global__ void zero_kernel() {
    int i = blockIdx.x * blockDim.x + threadIdx.x;
    if (i < N_NODES)          g_deg[i] = 0;
    if (i < G_GRAPHS * H_DIM) g_pool[i] = 0.f;
    if (i < G_GRAPHS)         g_cnt[i] = 0;
}

__global__ void degree_kernel(const int* __restrict__ ei) {
    int e = blockIdx.x * blockDim.x + threadIdx.x;
    if (e < E_EDGES) {
        int d = ei[E_EDGES + e];
        atomicAdd(&g_deg[d], 1);
    }
}

__global__ void dinv_kernel() {
    int i = blockIdx.x * blockDim.x + threadIdx.x;
    if (i < N_NODES) g_dinv[i] = rsqrtf((float)g_deg[i] + 1.0f);
}

// ---------------- GEMM: [N,128] @ [128,128] ----------------
// mode 0: out = relu(x @ W + bias)           -> g_h        (A = x param)
// mode 1: t = (g_h @ W) * dinv[row]; g_hw = t; g_agg = t   (self-loop init)
__global__ void __launch_bounds__(256) gemm_kernel(
    const float* __restrict__ A_in, const float* __restrict__ W,
    const float* __restrict__ bias, int mode)
{
    extern __shared__ float sm[];
    float* Ws = sm;                 // [128][128]
    float* As = sm + 128 * 128;     // [64][128]

    const float* A = (mode == 0) ? A_in : g_h;
    int tid  = threadIdx.x;
    int row0 = blockIdx.x * 64;

    // load W tile (16384 floats, coalesced float4)
    const float4* W4 = (const float4*)W;
    float4* Ws4 = (float4*)Ws;
#pragma unroll
    for (int i = 0; i < 16; i++) Ws4[tid + 256 * i] = W4[tid + 256 * i];

    // load A tile (64 rows x 128), zero-pad out-of-range rows
    float4* As4 = (float4*)As;
#pragma unroll
    for (int i = 0; i < 8; i++) {
        int idx = tid + 256 * i;          // float4 index, 32 per row
        int r   = idx >> 5;
        float4 v = make_float4(0.f, 0.f, 0.f, 0.f);
        if (row0 + r < N_NODES)
            v = ((const float4*)(A + (size_t)(row0 + r) * 128))[idx & 31];
        As4[idx] = v;
    }
    __syncthreads();

    int warp = tid >> 5, lane = tid & 31;
    float acc[8][4];
#pragma unroll
    for (int r = 0; r < 8; r++)
#pragma unroll
        for (int c = 0; c < 4; c++) acc[r][c] = 0.f;

    const float* Arow = As + warp * 8 * 128;
#pragma unroll 4
    for (int k = 0; k < 128; k++) {
        float4 wv = ((const float4*)(Ws + k * 128))[lane];
#pragma unroll
        for (int r = 0; r < 8; r++) {
            float a = Arow[r * 128 + k];
            acc[r][0] = fmaf(a, wv.x, acc[r][0]);
            acc[r][1] = fmaf(a, wv.y, acc[r][1]);
            acc[r][2] = fmaf(a, wv.z, acc[r][2]);
            acc[r][3] = fmaf(a, wv.w, acc[r][3]);
        }
    }

    if (mode == 0) {
        float4 bv = ((const float4*)bias)[lane];
#pragma unroll
        for (int r = 0; r < 8; r++) {
            int row = row0 + warp * 8 + r;
            if (row < N_NODES) {
                float4 o;
                o.x = fmaxf(acc[r][0] + bv.x, 0.f);
                o.y = fmaxf(acc[r][1] + bv.y, 0.f);
                o.z = fmaxf(acc[r][2] + bv.z, 0.f);
                o.w = fmaxf(acc[r][3] + bv.w, 0.f);
                ((float4*)(g_h + (size_t)row * 128))[lane] = o;
            }
        }
    } else {
#pragma unroll
        for (int r = 0; r < 8; r++) {
            int row = row0 + warp * 8 + r;
            if (row < N_NODES) {
                float dv = g_dinv[row];
                float4 o;
                o.x = acc[r][0] * dv;
                o.y = acc[r][1] * dv;
                o.z = acc[r][2] * dv;
                o.w = acc[r][3] * dv;
                ((float4*)(g_hw  + (size_t)row * 128))[lane] = o;
                ((float4*)(g_agg + (size_t)row * 128))[lane] = o;
            }
        }
    }
}

// ---------------- edge scatter: agg[dst] += hws[src] (warp per edge) ----------------
__global__ void edge_kernel(const int* __restrict__ ei) {
    unsigned gtid = blockIdx.x * blockDim.x + threadIdx.x;
    unsigned e    = gtid >> 5;
    int lane      = threadIdx.x & 31;
    if (e >= E_EDGES) return;
    int s = ei[e];
    int d = ei[E_EDGES + e];
    float4 v = ((const float4*)(g_hw + (size_t)s * 128))[lane];
    float* dp = g_agg + (size_t)d * 128 + lane * 4;
    atomicAdd(dp + 0, v.x);
    atomicAdd(dp + 1, v.y);
    atomicAdd(dp + 2, v.z);
    atomicAdd(dp + 3, v.w);
}

// ---------------- post: h = relu(BN(dinv[n]*agg + b)) ----------------
__global__ void post_kernel(const float* __restrict__ cb,
                            const float* __restrict__ gamma,
                            const float* __restrict__ beta,
                            const float* __restrict__ mean,
                            const float* __restrict__ var)
{
    int i = blockIdx.x * blockDim.x + threadIdx.x;   // over N*32 float4s
    if (i >= N_NODES * 32) return;
    int row = i >> 5;
    int c4  = (i & 31) * 4;
    float dv = g_dinv[row];
    float4 a = ((const float4*)g_agg)[i];
    float4 o;
    {
        float s = gamma[c4 + 0] * rsqrtf(var[c4 + 0] + BN_EPS);
        o.x = fmaxf((a.x * dv + cb[c4 + 0] - mean[c4 + 0]) * s + beta[c4 + 0], 0.f);
        s = gamma[c4 + 1] * rsqrtf(var[c4 + 1] + BN_EPS);
        o.y = fmaxf((a.y * dv + cb[c4 + 1] - mean[c4 + 1]) * s + beta[c4 + 1], 0.f);
        s = gamma[c4 + 2] * rsqrtf(var[c4 + 2] + BN_EPS);
        o.z = fmaxf((a.z * dv + cb[c4 + 2] - mean[c4 + 2]) * s + beta[c4 + 2], 0.f);
        s = gamma[c4 + 3] * rsqrtf(var[c4 + 3] + BN_EPS);
        o.w = fmaxf((a.w * dv + cb[c4 + 3] - mean[c4 + 3]) * s + beta[c4 + 3], 0.f);
    }
    ((float4*)g_h)[i] = o;
}

// ---------------- pooling: warp per node ----------------
__global__ void pool_kernel(const int* __restrict__ batch) {
    unsigned gtid = blockIdx.x * blockDim.x + threadIdx.x;
    unsigned n    = gtid >> 5;
    int lane      = threadIdx.x & 31;
    if (n >= N_NODES) return;
    int b = batch[n];
    float4 v = ((const float4*)(g_h + (size_t)n * 128))[lane];
    float* dp = g_pool + (size_t)b * 128 + lane * 4;
    atomicAdd(dp + 0, v.x);
    atomicAdd(dp + 1, v.y);
    atomicAdd(dp + 2, v.z);
    atomicAdd(dp + 3, v.w);
    if (lane == 0) atomicAdd(&g_cnt[b], 1);
}

// ---------------- MLP head: one block per graph ----------------
__global__ void mlp_kernel(const float* __restrict__ fc1w, const float* __restrict__ fc1b,
                           const float* __restrict__ fc2w, const float* __restrict__ fc2b,
                           float* __restrict__ out)
{
    __shared__ float gv[128];
    __shared__ float hid[64];
    int g = blockIdx.x;
    int t = threadIdx.x;           // 64 threads
    float cnt = fmaxf((float)g_cnt[g], 1.0f);
    float inv = 1.0f / cnt;
    gv[t]      = g_pool[g * 128 + t]      * inv;
    gv[t + 64] = g_pool[g * 128 + 64 + t] * inv;
    __syncthreads();
    float acc = fc1b[t];
#pragma unroll 8
    for (int k = 0; k < 128; k++) acc = fmaf(gv[k], fc1w[k * 64 + t], acc);
    hid[t] = fmaxf(acc, 0.f);
    __syncthreads();
    if (t < C_CLASSES) {
        float o = fc2b[t];
#pragma unroll
        for (int j = 0; j < 64; j++) o = fmaf(hid[j], fc2w[j * C_CLASSES + t], o);
        out[g * C_CLASSES + t] = o;
    }
}

__global__ void tail_kernel(float* __restrict__ out, int out_size) {
    int i = G_GRAPHS * C_CLASSES + blockIdx.x * blockDim.x + threadIdx.x;
    if (i < out_size) out[i] = 0.f;
}

// ---------------- launcher ----------------
extern "C" void kernel_launch(void* const* d_in, const int* in_sizes, int n_in,
                              void* d_out, int out_size)
{
    const float* x      = (const float*)d_in[0];
    const int*   ei     = (const int*)d_in[1];
    const int*   batch  = (const int*)d_in[2];
    const float* w_in   = (const float*)d_in[3];
    const float* b_in   = (const float*)d_in[4];
    const float* conv_w = (const float*)d_in[5];
    const float* conv_b = (const float*)d_in[6];
    const float* bn_g   = (const float*)d_in[7];
    const float* bn_b   = (const float*)d_in[8];
    const float* bn_m   = (const float*)d_in[9];
    const float* bn_v   = (const float*)d_in[10];
    const float* fc1w   = (const float*)d_in[11];
    const float* fc1b   = (const float*)d_in[12];
    const float* fc2w   = (const float*)d_in[13];
    const float* fc2b   = (const float*)d_in[14];
    float*       out    = (float*)d_out;

    const int SMEM = (128 * 128 + 64 * 128) * 4;   // 96 KB
    cudaFuncSetAttribute(gemm_kernel, cudaFuncAttributeMaxDynamicSharedMemorySize, SMEM);

    zero_kernel  <<<(N_NODES + 255) / 256, 256>>>();
    degree_kernel<<<(E_EDGES + 255) / 256, 256>>>(ei);
    dinv_kernel  <<<(N_NODES + 255) / 256, 256>>>();

    // input projection
    gemm_kernel<<<(N_NODES + 63) / 64, 256, SMEM>>>(x, w_in, b_in, 0);

    const unsigned edge_threads = (unsigned)E_EDGES * 32u;
    const unsigned edge_blocks  = (edge_threads + 255) / 256;

    for (int l = 0; l < L_LAYERS; l++) {
        gemm_kernel<<<(N_NODES + 63) / 64, 256, SMEM>>>(nullptr, conv_w + (size_t)l * 128 * 128, nullptr, 1);
        edge_kernel<<<edge_blocks, 256>>>(ei);
        post_kernel<<<(N_NODES * 32 + 255) / 256, 256>>>(conv_b + l * 128,
                                                         bn_g + l * 128, bn_b + l * 128,
                                                         bn_m + l * 128, bn_v + l * 128);
    }

    pool_kernel<<<((unsigned)N_NODES * 32u + 255) / 256, 256>>>(batch);
    mlp_kernel <<<G_GRAPHS, 64>>>(fc1w, fc1b, fc2w, fc2b, out);

    int tail = out_size - G_GRAPHS * C_CLASSES;
    if (tail > 0) tail_kernel<<<(tail + 255) / 256, 256>>>(out, out_size);
}

// round 4
// speedup vs baseline: 1.7085x; 1.7085x over previous
#include <cuda_runtime.h>

#define N_NODES   100000
#define E_EDGES   1600000
#define H_DIM     128
#define L_LAYERS  4
#define C_CLASSES 12
#define G_GRAPHS  512
#define BN_EPS    1e-5f

// ---------------- device scratch (no allocation allowed) ----------------
__device__ __align__(128) float g_h  [N_NODES * H_DIM];   // activations
__device__ __align__(128) float g_hw [N_NODES * H_DIM];   // (h @ W) * dinv[row]
__device__ __align__(128) float g_agg[N_NODES * H_DIM];   // aggregation buffer
__device__ __align__(128) float g_dinv[N_NODES];
__device__ __align__(128) int   g_deg [N_NODES];
__device__ __align__(128) float g_pool[G_GRAPHS * H_DIM];
__device__ __align__(128) int   g_cnt [G_GRAPHS];

// ---------------- zero / degree / dinv ----------------
__global__ void zero_kernel() {
    int i = blockIdx.x * blockDim.x + threadIdx.x;
    if (i < N_NODES)          g_deg[i] = 0;
    if (i < G_GRAPHS * H_DIM) g_pool[i] = 0.f;
    if (i < G_GRAPHS)         g_cnt[i] = 0;
}

__global__ void degree_kernel(const int* __restrict__ ei) {
    int e = blockIdx.x * blockDim.x + threadIdx.x;
    if (e < E_EDGES) {
        int d = ei[E_EDGES + e];
        atomicAdd(&g_deg[d], 1);
    }
}

__global__ void dinv_kernel() {
    int i = blockIdx.x * blockDim.x + threadIdx.x;
    if (i < N_NODES) g_dinv[i] = rsqrtf((float)g_deg[i] + 1.0f);
}

// ---------------- GEMM: [N,128] @ [128,128] ----------------
// mode 0: out = relu(x @ W + bias)           -> g_h        (A = x param)
// mode 1: t = (g_h @ W) * dinv[row]; g_hw = t; g_agg = t   (self-loop init)
__global__ void __launch_bounds__(256) gemm_kernel(
    const float* __restrict__ A_in, const float* __restrict__ W,
    const float* __restrict__ bias, int mode)
{
    extern __shared__ float sm[];
    float* Ws = sm;                 // [128][128]
    float* As = sm + 128 * 128;     // [64][128]

    const float* A = (mode == 0) ? A_in : g_h;
    int tid  = threadIdx.x;
    int row0 = blockIdx.x * 64;

    // load W tile (16384 floats, coalesced float4)
    const float4* W4 = (const float4*)W;
    float4* Ws4 = (float4*)Ws;
#pragma unroll
    for (int i = 0; i < 16; i++) Ws4[tid + 256 * i] = W4[tid + 256 * i];

    // load A tile (64 rows x 128), zero-pad out-of-range rows
    float4* As4 = (float4*)As;
#pragma unroll
    for (int i = 0; i < 8; i++) {
        int idx = tid + 256 * i;          // float4 index, 32 per row
        int r   = idx >> 5;
        float4 v = make_float4(0.f, 0.f, 0.f, 0.f);
        if (row0 + r < N_NODES)
            v = ((const float4*)(A + (size_t)(row0 + r) * 128))[idx & 31];
        As4[idx] = v;
    }
    __syncthreads();

    int warp = tid >> 5, lane = tid & 31;
    float acc[8][4];
#pragma unroll
    for (int r = 0; r < 8; r++)
#pragma unroll
        for (int c = 0; c < 4; c++) acc[r][c] = 0.f;

    const float* Arow = As + warp * 8 * 128;
#pragma unroll 4
    for (int k = 0; k < 128; k++) {
        float4 wv = ((const float4*)(Ws + k * 128))[lane];
#pragma unroll
        for (int r = 0; r < 8; r++) {
            float a = Arow[r * 128 + k];
            acc[r][0] = fmaf(a, wv.x, acc[r][0]);
            acc[r][1] = fmaf(a, wv.y, acc[r][1]);
            acc[r][2] = fmaf(a, wv.z, acc[r][2]);
            acc[r][3] = fmaf(a, wv.w, acc[r][3]);
        }
    }

    if (mode == 0) {
        float4 bv = ((const float4*)bias)[lane];
#pragma unroll
        for (int r = 0; r < 8; r++) {
            int row = row0 + warp * 8 + r;
            if (row < N_NODES) {
                float4 o;
                o.x = fmaxf(acc[r][0] + bv.x, 0.f);
                o.y = fmaxf(acc[r][1] + bv.y, 0.f);
                o.z = fmaxf(acc[r][2] + bv.z, 0.f);
                o.w = fmaxf(acc[r][3] + bv.w, 0.f);
                ((float4*)(g_h + (size_t)row * 128))[lane] = o;
            }
        }
    } else {
#pragma unroll
        for (int r = 0; r < 8; r++) {
            int row = row0 + warp * 8 + r;
            if (row < N_NODES) {
                float dv = g_dinv[row];
                float4 o;
                o.x = acc[r][0] * dv;
                o.y = acc[r][1] * dv;
                o.z = acc[r][2] * dv;
                o.w = acc[r][3] * dv;
                ((float4*)(g_hw  + (size_t)row * 128))[lane] = o;
                ((float4*)(g_agg + (size_t)row * 128))[lane] = o;
            }
        }
    }
}

// ---------------- edge scatter: agg[dst] += hws[src] (warp per edge) ----------------
__global__ void edge_kernel(const int* __restrict__ ei) {
    unsigned gtid = blockIdx.x * blockDim.x + threadIdx.x;
    unsigned e    = gtid >> 5;
    int lane      = threadIdx.x & 31;
    if (e >= E_EDGES) return;
    int s = ei[e];
    int d = ei[E_EDGES + e];
    float4 v = ((const float4*)(g_hw + (size_t)s * 128))[lane];
    float* dp = g_agg + (size_t)d * 128 + lane * 4;
    asm volatile("red.global.add.v4.f32 [%0], {%1,%2,%3,%4};"
                 :: "l"(dp), "f"(v.x), "f"(v.y), "f"(v.z), "f"(v.w) : "memory");
}

// ---------------- post: h = relu(BN(dinv[n]*agg + b)) ----------------
__global__ void post_kernel(const float* __restrict__ cb,
                            const float* __restrict__ gamma,
                            const float* __restrict__ beta,
                            const float* __restrict__ mean,
                            const float* __restrict__ var)
{
    int i = blockIdx.x * blockDim.x + threadIdx.x;   // over N*32 float4s
    if (i >= N_NODES * 32) return;
    int row = i >> 5;
    int c4  = (i & 31) * 4;
    float dv = g_dinv[row];
    float4 a = ((const float4*)g_agg)[i];
    float4 o;
    {
        float s = gamma[c4 + 0] * rsqrtf(var[c4 + 0] + BN_EPS);
        o.x = fmaxf((a.x * dv + cb[c4 + 0] - mean[c4 + 0]) * s + beta[c4 + 0], 0.f);
        s = gamma[c4 + 1] * rsqrtf(var[c4 + 1] + BN_EPS);
        o.y = fmaxf((a.y * dv + cb[c4 + 1] - mean[c4 + 1]) * s + beta[c4 + 1], 0.f);
        s = gamma[c4 + 2] * rsqrtf(var[c4 + 2] + BN_EPS);
        o.z = fmaxf((a.z * dv + cb[c4 + 2] - mean[c4 + 2]) * s + beta[c4 + 2], 0.f);
        s = gamma[c4 + 3] * rsqrtf(var[c4 + 3] + BN_EPS);
        o.w = fmaxf((a.w * dv + cb[c4 + 3] - mean[c4 + 3]) * s + beta[c4 + 3], 0.f);
    }
    ((float4*)g_h)[i] = o;
}

// ---------------- pooling: warp per node ----------------
__global__ void pool_kernel(const int* __restrict__ batch) {
    unsigned gtid = blockIdx.x * blockDim.x + threadIdx.x;
    unsigned n    = gtid >> 5;
    int lane      = threadIdx.x & 31;
    if (n >= N_NODES) return;
    int b = batch[n];
    float4 v = ((const float4*)(g_h + (size_t)n * 128))[lane];
    float* dp = g_pool + (size_t)b * 128 + lane * 4;
    asm volatile("red.global.add.v4.f32 [%0], {%1,%2,%3,%4};"
                 :: "l"(dp), "f"(v.x), "f"(v.y), "f"(v.z), "f"(v.w) : "memory");
    if (lane == 0) atomicAdd(&g_cnt[b], 1);
}

// ---------------- MLP head: one block per graph ----------------
__global__ void mlp_kernel(const float* __restrict__ fc1w, const float* __restrict__ fc1b,
                           const float* __restrict__ fc2w, const float* __restrict__ fc2b,
                           float* __restrict__ out)
{
    __shared__ float gv[128];
    __shared__ float hid[64];
    int g = blockIdx.x;
    int t = threadIdx.x;           // 64 threads
    float cnt = fmaxf((float)g_cnt[g], 1.0f);
    float inv = 1.0f / cnt;
    gv[t]      = g_pool[g * 128 + t]      * inv;
    gv[t + 64] = g_pool[g * 128 + 64 + t] * inv;
    __syncthreads();
    float acc = fc1b[t];
#pragma unroll 8
    for (int k = 0; k < 128; k++) acc = fmaf(gv[k], fc1w[k * 64 + t], acc);
    hid[t] = fmaxf(acc, 0.f);
    __syncthreads();
    if (t < C_CLASSES) {
        float o = fc2b[t];
#pragma unroll
        for (int j = 0; j < 64; j++) o = fmaf(hid[j], fc2w[j * C_CLASSES + t], o);
        out[g * C_CLASSES + t] = o;
    }
}

__global__ void tail_kernel(float* __restrict__ out, int out_size) {
    int i = G_GRAPHS * C_CLASSES + blockIdx.x * blockDim.x + threadIdx.x;
    if (i < out_size) out[i] = 0.f;
}

// ---------------- launcher ----------------
extern "C" void kernel_launch(void* const* d_in, const int* in_sizes, int n_in,
                              void* d_out, int out_size)
{
    const float* x      = (const float*)d_in[0];
    const int*   ei     = (const int*)d_in[1];
    const int*   batch  = (const int*)d_in[2];
    const float* w_in   = (const float*)d_in[3];
    const float* b_in   = (const float*)d_in[4];
    const float* conv_w = (const float*)d_in[5];
    const float* conv_b = (const float*)d_in[6];
    const float* bn_g   = (const float*)d_in[7];
    const float* bn_b   = (const float*)d_in[8];
    const float* bn_m   = (const float*)d_in[9];
    const float* bn_v   = (const float*)d_in[10];
    const float* fc1w   = (const float*)d_in[11];
    const float* fc1b   = (const float*)d_in[12];
    const float* fc2w   = (const float*)d_in[13];
    const float* fc2b   = (const float*)d_in[14];
    float*       out    = (float*)d_out;

    const int SMEM = (128 * 128 + 64 * 128) * 4;   // 96 KB
    cudaFuncSetAttribute(gemm_kernel, cudaFuncAttributeMaxDynamicSharedMemorySize, SMEM);

    zero_kernel  <<<(N_NODES + 255) / 256, 256>>>();
    degree_kernel<<<(E_EDGES + 255) / 256, 256>>>(ei);
    dinv_kernel  <<<(N_NODES + 255) / 256, 256>>>();

    // input projection
    gemm_kernel<<<(N_NODES + 63) / 64, 256, SMEM>>>(x, w_in, b_in, 0);

    const unsigned edge_threads = (unsigned)E_EDGES * 32u;
    const unsigned edge_blocks  = (edge_threads + 255) / 256;

    for (int l = 0; l < L_LAYERS; l++) {
        gemm_kernel<<<(N_NODES + 63) / 64, 256, SMEM>>>(nullptr, conv_w + (size_t)l * 128 * 128, nullptr, 1);
        edge_kernel<<<edge_blocks, 256>>>(ei);
        post_kernel<<<(N_NODES * 32 + 255) / 256, 256>>>(conv_b + l * 128,
                                                         bn_g + l * 128, bn_b + l * 128,
                                                         bn_m + l * 128, bn_v + l * 128);
    }

    pool_kernel<<<((unsigned)N_NODES * 32u + 255) / 256, 256>>>(batch);
    mlp_kernel <<<G_GRAPHS, 64>>>(fc1w, fc1b, fc2w, fc2b, out);

    int tail = out_size - G_GRAPHS * C_CLASSES;
    if (tail > 0) tail_kernel<<<(tail + 255) / 256, 256>>>(out, out_size);
}

// round 5
// speedup vs baseline: 2.3893x; 1.3985x over previous
#include <cuda_runtime.h>

#define N_NODES   100000
#define E_EDGES   1600000
#define H_DIM     128
#define L_LAYERS  4
#define C_CLASSES 12
#define G_GRAPHS  512
#define BN_EPS    1e-5f

#define SCAN_T    1024
#define CHUNK     ((N_NODES + SCAN_T - 1) / SCAN_T)   // 98

// ---------------- device scratch (no allocation allowed) ----------------
__device__ __align__(128) float g_h  [N_NODES * H_DIM];   // activations
__device__ __align__(128) float g_hw [N_NODES * H_DIM];   // (h @ W) * dinv[row]
__device__ __align__(128) float g_dinv[N_NODES];
__device__ __align__(128) int   g_deg [N_NODES];
__device__ __align__(128) int   g_rowstart[N_NODES + 1];
__device__ __align__(128) int   g_cursor  [N_NODES];
__device__ __align__(128) int   g_csr_src [E_EDGES];
__device__ __align__(128) float g_pool[G_GRAPHS * H_DIM];
__device__ __align__(128) int   g_cnt [G_GRAPHS];

// ---------------- zero / degree / dinv ----------------
__global__ void zero_kernel() {
    int i = blockIdx.x * blockDim.x + threadIdx.x;
    if (i < N_NODES)          g_deg[i] = 0;
    if (i < G_GRAPHS * H_DIM) g_pool[i] = 0.f;
    if (i < G_GRAPHS)         g_cnt[i] = 0;
}

__global__ void degree_kernel(const int* __restrict__ ei) {
    int e = blockIdx.x * blockDim.x + threadIdx.x;
    if (e < E_EDGES) atomicAdd(&g_deg[ei[E_EDGES + e]], 1);
}

// single-block exclusive scan of g_deg -> g_rowstart / g_cursor, plus dinv
__global__ void __launch_bounds__(SCAN_T) scan_kernel() {
    __shared__ int part[SCAN_T];
    int t  = threadIdx.x;
    int lo = t * CHUNK;
    int hi = min(lo + CHUNK, N_NODES);
    int s = 0;
    for (int i = lo; i < hi; i++) s += g_deg[i];
    part[t] = s;
    __syncthreads();
    // Kogge-Stone inclusive scan
    for (int d = 1; d < SCAN_T; d <<= 1) {
        int v = (t >= d) ? part[t - d] : 0;
        __syncthreads();
        part[t] += v;
        __syncthreads();
    }
    int run = part[t] - s;   // exclusive prefix for this chunk
    for (int i = lo; i < hi; i++) {
        g_rowstart[i] = run;
        g_cursor[i]   = run;
        int dg = g_deg[i];
        g_dinv[i] = rsqrtf((float)dg + 1.0f);
        run += dg;
    }
    if (t == SCAN_T - 1) g_rowstart[N_NODES] = run;
}

__global__ void fill_csr_kernel(const int* __restrict__ ei) {
    int e = blockIdx.x * blockDim.x + threadIdx.x;
    if (e < E_EDGES) {
        int s = ei[e];
        int d = ei[E_EDGES + e];
        int pos = atomicAdd(&g_cursor[d], 1);
        g_csr_src[pos] = s;
    }
}

// ---------------- GEMM: [N,128] @ [128,128] ----------------
// mode 0: g_h  = relu(x @ W + bias)          (A = x param)
// mode 1: g_hw = (g_h @ W) * dinv[row]
__global__ void __launch_bounds__(256) gemm_kernel(
    const float* __restrict__ A_in, const float* __restrict__ W,
    const float* __restrict__ bias, int mode)
{
    extern __shared__ float sm[];
    float* Ws = sm;                 // [128][128]
    float* As = sm + 128 * 128;     // [64][128]

    const float* A = (mode == 0) ? A_in : g_h;
    int tid  = threadIdx.x;
    int row0 = blockIdx.x * 64;

    const float4* W4 = (const float4*)W;
    float4* Ws4 = (float4*)Ws;
#pragma unroll
    for (int i = 0; i < 16; i++) Ws4[tid + 256 * i] = W4[tid + 256 * i];

    float4* As4 = (float4*)As;
#pragma unroll
    for (int i = 0; i < 8; i++) {
        int idx = tid + 256 * i;
        int r   = idx >> 5;
        float4 v = make_float4(0.f, 0.f, 0.f, 0.f);
        if (row0 + r < N_NODES)
            v = ((const float4*)(A + (size_t)(row0 + r) * 128))[idx & 31];
        As4[idx] = v;
    }
    __syncthreads();

    int warp = tid >> 5, lane = tid & 31;
    float acc[8][4];
#pragma unroll
    for (int r = 0; r < 8; r++)
#pragma unroll
        for (int c = 0; c < 4; c++) acc[r][c] = 0.f;

    const float* Arow = As + warp * 8 * 128;
#pragma unroll 4
    for (int k = 0; k < 128; k++) {
        float4 wv = ((const float4*)(Ws + k * 128))[lane];
#pragma unroll
        for (int r = 0; r < 8; r++) {
            float a = Arow[r * 128 + k];
            acc[r][0] = fmaf(a, wv.x, acc[r][0]);
            acc[r][1] = fmaf(a, wv.y, acc[r][1]);
            acc[r][2] = fmaf(a, wv.z, acc[r][2]);
            acc[r][3] = fmaf(a, wv.w, acc[r][3]);
        }
    }

    if (mode == 0) {
        float4 bv = ((const float4*)bias)[lane];
#pragma unroll
        for (int r = 0; r < 8; r++) {
            int row = row0 + warp * 8 + r;
            if (row < N_NODES) {
                float4 o;
                o.x = fmaxf(acc[r][0] + bv.x, 0.f);
                o.y = fmaxf(acc[r][1] + bv.y, 0.f);
                o.z = fmaxf(acc[r][2] + bv.z, 0.f);
                o.w = fmaxf(acc[r][3] + bv.w, 0.f);
                ((float4*)(g_h + (size_t)row * 128))[lane] = o;
            }
        }
    } else {
#pragma unroll
        for (int r = 0; r < 8; r++) {
            int row = row0 + warp * 8 + r;
            if (row < N_NODES) {
                float dv = g_dinv[row];
                float4 o;
                o.x = acc[r][0] * dv;
                o.y = acc[r][1] * dv;
                o.z = acc[r][2] * dv;
                o.w = acc[r][3] * dv;
                ((float4*)(g_hw + (size_t)row * 128))[lane] = o;
            }
        }
    }
}

// ---------------- fused aggregation + BN + ReLU (warp per dst node) ----------------
// h[n] = relu( BN( ( g_hw[n] + sum_{src->n} g_hw[src] ) * dinv[n] + conv_b ) )
__global__ void __launch_bounds__(256) agg_kernel(
    const float* __restrict__ cb,
    const float* __restrict__ gamma,
    const float* __restrict__ beta,
    const float* __restrict__ mean,
    const float* __restrict__ var)
{
    unsigned gtid = blockIdx.x * blockDim.x + threadIdx.x;
    unsigned n    = gtid >> 5;
    int lane      = threadIdx.x & 31;
    if (n >= N_NODES) return;

    float4 acc = ((const float4*)(g_hw + (size_t)n * 128))[lane];   // self term

    int start = g_rowstart[n];
    int end   = g_rowstart[n + 1];
    for (int base = start; base < end; base += 32) {
        int cnt = min(32, end - base);
        int src = (base + lane < end) ? g_csr_src[base + lane] : 0;
#pragma unroll 4
        for (int j = 0; j < cnt; j++) {
            int s = __shfl_sync(0xffffffffu, src, j);
            float4 v = __ldg((const float4*)(g_hw + (size_t)s * 128) + lane);
            acc.x += v.x; acc.y += v.y; acc.z += v.z; acc.w += v.w;
        }
    }

    float dv = g_dinv[n];
    int c4   = lane * 4;
    float4 o;
    {
        float s = gamma[c4 + 0] * rsqrtf(var[c4 + 0] + BN_EPS);
        o.x = fmaxf((acc.x * dv + cb[c4 + 0] - mean[c4 + 0]) * s + beta[c4 + 0], 0.f);
        s = gamma[c4 + 1] * rsqrtf(var[c4 + 1] + BN_EPS);
        o.y = fmaxf((acc.y * dv + cb[c4 + 1] - mean[c4 + 1]) * s + beta[c4 + 1], 0.f);
        s = gamma[c4 + 2] * rsqrtf(var[c4 + 2] + BN_EPS);
        o.z = fmaxf((acc.z * dv + cb[c4 + 2] - mean[c4 + 2]) * s + beta[c4 + 2], 0.f);
        s = gamma[c4 + 3] * rsqrtf(var[c4 + 3] + BN_EPS);
        o.w = fmaxf((acc.w * dv + cb[c4 + 3] - mean[c4 + 3]) * s + beta[c4 + 3], 0.f);
    }
    ((float4*)(g_h + (size_t)n * 128))[lane] = o;
}

// ---------------- pooling: warp per node ----------------
__global__ void pool_kernel(const int* __restrict__ batch) {
    unsigned gtid = blockIdx.x * blockDim.x + threadIdx.x;
    unsigned n    = gtid >> 5;
    int lane      = threadIdx.x & 31;
    if (n >= N_NODES) return;
    int b = batch[n];
    float4 v = ((const float4*)(g_h + (size_t)n * 128))[lane];
    float* dp = g_pool + (size_t)b * 128 + lane * 4;
    asm volatile("red.global.add.v4.f32 [%0], {%1,%2,%3,%4};"
                 :: "l"(dp), "f"(v.x), "f"(v.y), "f"(v.z), "f"(v.w) : "memory");
    if (lane == 0) atomicAdd(&g_cnt[b], 1);
}

// ---------------- MLP head: one block per graph ----------------
__global__ void mlp_kernel(const float* __restrict__ fc1w, const float* __restrict__ fc1b,
                           const float* __restrict__ fc2w, const float* __restrict__ fc2b,
                           float* __restrict__ out)
{
    __shared__ float gv[128];
    __shared__ float hid[64];
    int g = blockIdx.x;
    int t = threadIdx.x;           // 64 threads
    float cnt = fmaxf((float)g_cnt[g], 1.0f);
    float inv = 1.0f / cnt;
    gv[t]      = g_pool[g * 128 + t]      * inv;
    gv[t + 64] = g_pool[g * 128 + 64 + t] * inv;
    __syncthreads();
    float acc = fc1b[t];
#pragma unroll 8
    for (int k = 0; k < 128; k++) acc = fmaf(gv[k], fc1w[k * 64 + t], acc);
    hid[t] = fmaxf(acc, 0.f);
    __syncthreads();
    if (t < C_CLASSES) {
        float o = fc2b[t];
#pragma unroll
        for (int j = 0; j < 64; j++) o = fmaf(hid[j], fc2w[j * C_CLASSES + t], o);
        out[g * C_CLASSES + t] = o;
    }
}

__global__ void tail_kernel(float* __restrict__ out, int out_size) {
    int i = G_GRAPHS * C_CLASSES + blockIdx.x * blockDim.x + threadIdx.x;
    if (i < out_size) out[i] = 0.f;
}

// ---------------- launcher ----------------
extern "C" void kernel_launch(void* const* d_in, const int* in_sizes, int n_in,
                              void* d_out, int out_size)
{
    const float* x      = (const float*)d_in[0];
    const int*   ei     = (const int*)d_in[1];
    const int*   batch  = (const int*)d_in[2];
    const float* w_in   = (const float*)d_in[3];
    const float* b_in   = (const float*)d_in[4];
    const float* conv_w = (const float*)d_in[5];
    const float* conv_b = (const float*)d_in[6];
    const float* bn_g   = (const float*)d_in[7];
    const float* bn_b   = (const float*)d_in[8];
    const float* bn_m   = (const float*)d_in[9];
    const float* bn_v   = (const float*)d_in[10];
    const float* fc1w   = (const float*)d_in[11];
    const float* fc1b   = (const float*)d_in[12];
    const float* fc2w   = (const float*)d_in[13];
    const float* fc2b   = (const float*)d_in[14];
    float*       out    = (float*)d_out;

    const int SMEM = (128 * 128 + 64 * 128) * 4;   // 96 KB
    cudaFuncSetAttribute(gemm_kernel, cudaFuncAttributeMaxDynamicSharedMemorySize, SMEM);

    zero_kernel    <<<(N_NODES + 255) / 256, 256>>>();
    degree_kernel  <<<(E_EDGES + 255) / 256, 256>>>(ei);
    scan_kernel    <<<1, SCAN_T>>>();
    fill_csr_kernel<<<(E_EDGES + 255) / 256, 256>>>(ei);

    // input projection
    gemm_kernel<<<(N_NODES + 63) / 64, 256, SMEM>>>(x, w_in, b_in, 0);

    const unsigned node_warp_blocks = ((unsigned)N_NODES * 32u + 255) / 256;

    for (int l = 0; l < L_LAYERS; l++) {
        gemm_kernel<<<(N_NODES + 63) / 64, 256, SMEM>>>(nullptr, conv_w + (size_t)l * 128 * 128, nullptr, 1);
        agg_kernel <<<node_warp_blocks, 256>>>(conv_b + l * 128,
                                               bn_g + l * 128, bn_b + l * 128,
                                               bn_m + l * 128, bn_v + l * 128);
    }

    pool_kernel<<<node_warp_blocks, 256>>>(batch);
    mlp_kernel <<<G_GRAPHS, 64>>>(fc1w, fc1b, fc2w, fc2b, out);

    int tail = out_size - G_GRAPHS * C_CLASSES;
    if (tail > 0) tail_kernel<<<(tail + 255) / 256, 256>>>(out, out_size);
}